// round 1
// baseline (speedup 1.0000x reference)
#include <cuda_runtime.h>

#define BB 4
#define SS 2048
#define DD 1024
#define HH 16
#define DKK 64
#define MR (BB*SS)   // 8192 rows

// Scratch (device globals — allocation-free rule)
__device__ float g_w[4][DD*DD];     // [0..2]: per-head proj weights rearranged to [D, H*DK]; [3]: wo^T
__device__ float g_qh[MR*DD];       // [B,S,H,DK] flat = [8192,1024]
__device__ float g_kh[MR*DD];
__device__ float g_vh[MR*DD];
__device__ float g_M[BB*HH*DKK*DKK];// per-(b,h) Kh^T Vh  [64][64]
__device__ float g_heads[MR*DD];    // post-softmax concat heads [8192,1024]

// ---------------------------------------------------------------------------
// Rearrange weights: wq_w/wk_w/wv_w [H,D,DK] -> [D, H*DK]; wo_w [D,D] -> transpose
// ---------------------------------------------------------------------------
__global__ void prep_weights(const float* __restrict__ wq, const float* __restrict__ wk,
                             const float* __restrict__ wv, const float* __restrict__ wo) {
    int idx = blockIdx.x * blockDim.x + threadIdx.x;   // 0 .. D*D-1
    int d = idx >> 10, n = idx & 1023;
    int h = n >> 6, kk = n & 63;
    int src = h * (DD * DKK) + d * DKK + kk;
    g_w[0][idx] = wq[src];
    g_w[1][idx] = wk[src];
    g_w[2][idx] = wv[src];
    g_w[3][idx] = wo[n * DD + d];   // woT[d][n] = wo[n][d]
}

// ---------------------------------------------------------------------------
// Generic fp32 GEMM: C[8192,1024] = A[8192,1024] @ g_w[widx][1024,1024] + bias
// widx 0/1/2 -> write g_qh/g_kh/g_vh (A = param); widx 3 -> A = g_heads, C = param
// Tile: BM=128, BN=128, BK=8, thread tile 8x8, 256 threads.
// ---------------------------------------------------------------------------
__global__ __launch_bounds__(256) void gemm_bias(const float* __restrict__ Ain,
                                                 const float* __restrict__ bias,
                                                 float* __restrict__ Cout,
                                                 int widx) {
    const float* A = (widx < 3) ? Ain : g_heads;
    float* C = (widx == 0) ? g_qh : (widx == 1) ? g_kh : (widx == 2) ? g_vh : Cout;
    const float* Wt = g_w[widx];

    __shared__ float As[8][128];
    __shared__ float Bs[8][128];

    int tid = threadIdx.x;
    int bm = blockIdx.y * 128;
    int bn = blockIdx.x * 128;

    int a_row = tid >> 1;            // 0..127
    int a_col = (tid & 1) << 2;      // 0 or 4
    int b_row = tid >> 5;            // 0..7
    int b_col = (tid & 31) << 2;     // 0..124

    const float* Ap = A + (size_t)(bm + a_row) * DD + a_col;
    const float* Bp = Wt + (size_t)b_row * DD + bn + b_col;

    float acc[8][8];
    #pragma unroll
    for (int i = 0; i < 8; i++)
        #pragma unroll
        for (int j = 0; j < 8; j++) acc[i][j] = 0.0f;

    int m_loc = (tid >> 4) << 3;
    int n_loc = (tid & 15) << 3;

    for (int k0 = 0; k0 < DD; k0 += 8) {
        float4 av = *(const float4*)(Ap + k0);
        float4 bv = *(const float4*)(Bp + (size_t)k0 * DD);
        __syncthreads();
        As[a_col + 0][a_row] = av.x;
        As[a_col + 1][a_row] = av.y;
        As[a_col + 2][a_row] = av.z;
        As[a_col + 3][a_row] = av.w;
        *(float4*)&Bs[b_row][b_col] = bv;
        __syncthreads();
        #pragma unroll
        for (int kk = 0; kk < 8; kk++) {
            float4 a0 = *(const float4*)&As[kk][m_loc];
            float4 a1 = *(const float4*)&As[kk][m_loc + 4];
            float4 b0 = *(const float4*)&Bs[kk][n_loc];
            float4 b1 = *(const float4*)&Bs[kk][n_loc + 4];
            float a[8] = {a0.x, a0.y, a0.z, a0.w, a1.x, a1.y, a1.z, a1.w};
            float b[8] = {b0.x, b0.y, b0.z, b0.w, b1.x, b1.y, b1.z, b1.w};
            #pragma unroll
            for (int i = 0; i < 8; i++)
                #pragma unroll
                for (int j = 0; j < 8; j++)
                    acc[i][j] = fmaf(a[i], b[j], acc[i][j]);
        }
    }

    #pragma unroll
    for (int i = 0; i < 8; i++) {
        size_t row = (size_t)(bm + m_loc + i) * DD;
        #pragma unroll
        for (int j = 0; j < 8; j += 4) {
            int col = bn + n_loc + j;
            float4 r;
            r.x = acc[i][j + 0] + bias[col + 0];
            r.y = acc[i][j + 1] + bias[col + 1];
            r.z = acc[i][j + 2] + bias[col + 2];
            r.w = acc[i][j + 3] + bias[col + 3];
            *(float4*)&C[row + col] = r;
        }
    }
}

// ---------------------------------------------------------------------------
// g_M[b,h] = Kh^T @ Vh   ([64,64], reduce over S=2048). One block per (b,h).
// ---------------------------------------------------------------------------
__global__ __launch_bounds__(256) void kv_outer() {
    int bh = blockIdx.x;
    int b = bh >> 4, h = bh & 15;
    const float* Kb = g_kh + (size_t)b * SS * DD + h * DKK;
    const float* Vb = g_vh + (size_t)b * SS * DD + h * DKK;

    __shared__ float ks[32][64];
    __shared__ float vs[32][64];

    int tid = threadIdx.x;
    int lrow = tid >> 3;            // 0..31
    int lcol = (tid & 7) << 3;      // 0,8,..,56
    int tj = (tid >> 4) << 2;       // j base 0..60
    int tk = (tid & 15) << 2;       // k base 0..60

    float acc[4][4];
    #pragma unroll
    for (int i = 0; i < 4; i++)
        #pragma unroll
        for (int j = 0; j < 4; j++) acc[i][j] = 0.0f;

    for (int s0 = 0; s0 < SS; s0 += 32) {
        __syncthreads();
        const float* kp = Kb + (size_t)(s0 + lrow) * DD + lcol;
        const float* vp = Vb + (size_t)(s0 + lrow) * DD + lcol;
        *(float4*)&ks[lrow][lcol]     = *(const float4*)kp;
        *(float4*)&ks[lrow][lcol + 4] = *(const float4*)(kp + 4);
        *(float4*)&vs[lrow][lcol]     = *(const float4*)vp;
        *(float4*)&vs[lrow][lcol + 4] = *(const float4*)(vp + 4);
        __syncthreads();
        #pragma unroll
        for (int ss = 0; ss < 32; ss++) {
            float4 kj4 = *(const float4*)&ks[ss][tj];
            float4 vk4 = *(const float4*)&vs[ss][tk];
            float kj[4] = {kj4.x, kj4.y, kj4.z, kj4.w};
            float vk[4] = {vk4.x, vk4.y, vk4.z, vk4.w};
            #pragma unroll
            for (int i = 0; i < 4; i++)
                #pragma unroll
                for (int j = 0; j < 4; j++)
                    acc[i][j] = fmaf(kj[i], vk[j], acc[i][j]);
        }
    }

    float* Mout = g_M + (size_t)bh * (DKK * DKK);
    #pragma unroll
    for (int i = 0; i < 4; i++)
        #pragma unroll
        for (int j = 0; j < 4; j++)
            Mout[(tj + i) * DKK + tk + j] = acc[i][j];
}

// ---------------------------------------------------------------------------
// heads[b,s,h*64+k] = softmax_k( (Qh[b,h,s,:] @ M[b,h]) / 8 )
// One block per (b,h, 256-row chunk); 8 warps, 1 row per warp per iter.
// ---------------------------------------------------------------------------
__global__ __launch_bounds__(256) void qm_softmax() {
    int bh = blockIdx.x;
    int b = bh >> 4, h = bh & 15;

    __shared__ float Ms[DKK * DKK];
    __shared__ float qs[8][DKK];

    int tid = threadIdx.x;
    const float4* Msrc = (const float4*)(g_M + (size_t)bh * (DKK * DKK));
    for (int i = tid; i < (DKK * DKK) / 4; i += 256)
        ((float4*)Ms)[i] = Msrc[i];
    __syncthreads();

    int warp = tid >> 5, lane = tid & 31;
    int sbase = blockIdx.y * 256;

    for (int it = 0; it < 32; it++) {
        int s = sbase + (it << 3) + warp;
        const float* qrow = g_qh + ((size_t)(b * SS + s)) * DD + h * DKK;
        qs[warp][lane]      = qrow[lane];
        qs[warp][lane + 32] = qrow[lane + 32];
        __syncwarp();

        float o0 = 0.0f, o1 = 0.0f;
        #pragma unroll
        for (int j = 0; j < 64; j++) {
            float qv = qs[warp][j];
            o0 = fmaf(qv, Ms[(j << 6) + lane],      o0);
            o1 = fmaf(qv, Ms[(j << 6) + lane + 32], o1);
        }
        o0 *= 0.125f;  // 1/sqrt(64)
        o1 *= 0.125f;

        float mx = fmaxf(o0, o1);
        #pragma unroll
        for (int off = 16; off; off >>= 1)
            mx = fmaxf(mx, __shfl_xor_sync(0xffffffffu, mx, off));
        float e0 = __expf(o0 - mx), e1 = __expf(o1 - mx);
        float sm = e0 + e1;
        #pragma unroll
        for (int off = 16; off; off >>= 1)
            sm += __shfl_xor_sync(0xffffffffu, sm, off);
        float inv = 1.0f / sm;

        float* hrow = g_heads + ((size_t)(b * SS + s)) * DD + h * DKK;
        hrow[lane]      = e0 * inv;
        hrow[lane + 32] = e1 * inv;
        __syncwarp();
    }
}

// ---------------------------------------------------------------------------
extern "C" void kernel_launch(void* const* d_in, const int* in_sizes, int n_in,
                              void* d_out, int out_size) {
    const float* q    = (const float*)d_in[0];
    const float* k    = (const float*)d_in[1];
    const float* v    = (const float*)d_in[2];
    const float* wq_w = (const float*)d_in[3];
    const float* wq_b = (const float*)d_in[4];
    const float* wk_w = (const float*)d_in[5];
    const float* wk_b = (const float*)d_in[6];
    const float* wv_w = (const float*)d_in[7];
    const float* wv_b = (const float*)d_in[8];
    const float* wo_w = (const float*)d_in[9];
    const float* wo_b = (const float*)d_in[10];
    float* out = (float*)d_out;

    prep_weights<<<(DD * DD) / 256, 256>>>(wq_w, wk_w, wv_w, wo_w);

    dim3 gg(DD / 128, MR / 128);
    gemm_bias<<<gg, 256>>>(q, wq_b, nullptr, 0);
    gemm_bias<<<gg, 256>>>(k, wk_b, nullptr, 1);
    gemm_bias<<<gg, 256>>>(v, wv_b, nullptr, 2);

    kv_outer<<<BB * HH, 256>>>();
    qm_softmax<<<dim3(BB * HH, SS / 256), 256>>>();

    gemm_bias<<<gg, 256>>>(nullptr, wo_b, out, 3);
}

// round 3
// speedup vs baseline: 1.3555x; 1.3555x over previous
#include <cuda_runtime.h>
#include <cstdint>

#define BB 4
#define SS 2048
#define DD 1024
#define HH 16
#define DKK 64
#define MR (BB*SS)   // 8192

#define MT 128
#define NT 128
#define KC 32
#define NCH (DD/KC)     // 32
#define ROWB 144        // smem bytes per 32-float row (128 + 16 pad)
#define TILEB (128*ROWB) // 18432
#define STAGEB (4*TILEB) // Ahi|Alo|Bhi|Blo
#define NSTG 3

// ---------------- device scratch ----------------
__device__ float g_wt[4][2][DD*DD];   // weights: [widx][hi/lo][n*1024+k]
__device__ float g_Ahi[MR*DD];
__device__ float g_Alo[MR*DD];
__device__ float g_qh[MR*DD];
__device__ float g_kh[MR*DD];
__device__ float g_vh[MR*DD];
__device__ float g_Mpart[BB*HH*8][DKK*DKK];
__device__ float g_M[BB*HH][DKK*DKK];

// ---------------- helpers ----------------
__device__ __forceinline__ float tf32r(float x) {
    uint32_t u;
    asm("cvt.rna.tf32.f32 %0, %1;" : "=r"(u) : "f"(x));
    return __uint_as_float(u);
}
__device__ __forceinline__ uint32_t smem_u32(const void* p) {
    uint32_t a;
    asm("{ .reg .u64 t; cvta.to.shared.u64 t, %1; cvt.u32.u64 %0, t; }" : "=r"(a) : "l"(p));
    return a;
}
#define CP16(dst, src) asm volatile( \
    "cp.async.cg.shared.global [%0], [%1], 16;" :: "r"(dst), "l"(src))
#define CPC() asm volatile("cp.async.commit_group;" ::: "memory")
#define CPW(n) asm volatile("cp.async.wait_group %0;" :: "n"(n) : "memory")
#define LDSM4(r, a) asm volatile( \
    "ldmatrix.sync.aligned.m8n8.x4.shared.b16 {%0,%1,%2,%3}, [%4];" \
    : "=r"((r)[0]), "=r"((r)[1]), "=r"((r)[2]), "=r"((r)[3]) : "r"(a))
#define MMA168(d, a, b0, b1) asm volatile( \
    "mma.sync.aligned.m16n8k8.row.col.f32.tf32.tf32.f32 " \
    "{%0,%1,%2,%3}, {%4,%5,%6,%7}, {%8,%9}, {%0,%1,%2,%3};" \
    : "+f"((d)[0]), "+f"((d)[1]), "+f"((d)[2]), "+f"((d)[3]) \
    : "r"((a)[0]), "r"((a)[1]), "r"((a)[2]), "r"((a)[3]), "r"(b0), "r"(b1))

// ---------------------------------------------------------------------------
// weights: split+transpose into tf32 hi/lo pairs, layout [n][k]
// ---------------------------------------------------------------------------
__global__ void prep_split(const float* __restrict__ wq, const float* __restrict__ wk,
                           const float* __restrict__ wv, const float* __restrict__ wo) {
    int idx = blockIdx.x * blockDim.x + threadIdx.x;   // n*1024 + k
    int n = idx >> 10, k = idx & 1023;
    int h = n >> 6, dk = n & 63;
    int src = h * (DD * DKK) + k * DKK + dk;           // w[h][k][dk]
    float v0 = wq[src], v1 = wk[src], v2 = wv[src], v3 = wo[n * DD + k];
    float h0 = tf32r(v0), h1 = tf32r(v1), h2 = tf32r(v2), h3 = tf32r(v3);
    g_wt[0][0][idx] = h0; g_wt[0][1][idx] = tf32r(v0 - h0);
    g_wt[1][0][idx] = h1; g_wt[1][1][idx] = tf32r(v1 - h1);
    g_wt[2][0][idx] = h2; g_wt[2][1][idx] = tf32r(v2 - h2);
    g_wt[3][0][idx] = h3; g_wt[3][1][idx] = tf32r(v3 - h3);
}

// split an activation matrix into g_Ahi / g_Alo
__global__ void split_src(const float* __restrict__ src) {
    int idx = blockIdx.x * blockDim.x + threadIdx.x;
    float v = src[idx];
    float h = tf32r(v);
    g_Ahi[idx] = h;
    g_Alo[idx] = tf32r(v - h);
}

// ---------------------------------------------------------------------------
// 3xTF32 mma.sync GEMM: C[8192,1024] = (Ahi+Alo) @ W(widx)^T + bias
// CTA 128x128, warp 64x32, K-chunk 32, 3-stage cp.async pipeline.
// ---------------------------------------------------------------------------
__global__ __launch_bounds__(256) void mma_gemm(const float* __restrict__ bias,
                                                float* __restrict__ Cout, int widx) {
    extern __shared__ char smem[];
    float* C = (widx == 0) ? g_qh : (widx == 1) ? g_kh : (widx == 2) ? g_vh : Cout;
    const float* Bhi = g_wt[widx][0];
    const float* Blo = g_wt[widx][1];

    const uint32_t s0 = smem_u32(smem);
    const int tid = threadIdx.x;
    const int wid = tid >> 5, lane = tid & 31;
    const int bm = blockIdx.y * MT, bn = blockIdx.x * NT;
    const int m0 = (wid >> 2) * 64;      // warp M offset
    const int n0 = (wid & 3) * 32;       // warp N offset

    // cp.async source/dest mapping: 16 segments of 16B per thread per stage
    const int lrow = tid >> 3;           // 0..31 base row (4 rows-groups of 32)
    const int lc4 = tid & 7;             // 16B segment within row

    // ldmatrix lane addressing
    const int arow = (lane & 7) + ((lane >> 3) & 1) * 8;
    const uint32_t akoff = (lane >> 4) * 16;
    const uint32_t aLane = (uint32_t)(m0 + arow) * ROWB + akoff;
    const int nrow = (lane & 7) + (lane >> 4) * 8;
    const uint32_t bkoff = ((lane >> 3) & 1) * 16;
    const uint32_t bLane = (uint32_t)(n0 + nrow) * ROWB + bkoff;

    float acc[4][4][4];
    #pragma unroll
    for (int i = 0; i < 4; i++)
        #pragma unroll
        for (int j = 0; j < 4; j++)
            #pragma unroll
            for (int r = 0; r < 4; r++) acc[i][j][r] = 0.0f;

    // ---- stage loader ----
    auto load_stage = [&](int stg, int ch) {
        const int k0 = ch * KC;
        uint32_t sb = s0 + stg * STAGEB;
        #pragma unroll
        for (int i = 0; i < 4; i++) {
            int row = lrow + i * 32;                    // 0..127
            uint32_t soff = (uint32_t)row * ROWB + lc4 * 16;
            size_t gA = (size_t)(bm + row) * DD + k0 + lc4 * 4;
            size_t gB = (size_t)(bn + row) * DD + k0 + lc4 * 4;
            CP16(sb + soff,             g_Ahi + gA);
            CP16(sb + TILEB + soff,     g_Alo + gA);
            CP16(sb + 2 * TILEB + soff, Bhi + gB);
            CP16(sb + 3 * TILEB + soff, Blo + gB);
        }
    };

    load_stage(0, 0); CPC();
    load_stage(1, 1); CPC();

    for (int c = 0; c < NCH; ++c) {
        __syncthreads();                       // buffer-reuse guard
        if (c + 2 < NCH) load_stage((c + 2) % NSTG, c + 2);
        CPC();
        CPW(2);
        __syncthreads();

        uint32_t sb = s0 + (c % NSTG) * STAGEB;
        uint32_t sAhi = sb + aLane;
        uint32_t sAlo = sb + TILEB + aLane;
        uint32_t sBhi = sb + 2 * TILEB + bLane;
        uint32_t sBlo = sb + 3 * TILEB + bLane;

        #pragma unroll
        for (int ks = 0; ks < 4; ks++) {
            const uint32_t ko = ks * 32;
            uint32_t af[4][4], bf[2][4];
            // hi*hi
            #pragma unroll
            for (int i = 0; i < 4; i++) LDSM4(af[i], sAhi + i * (16 * ROWB) + ko);
            #pragma unroll
            for (int j = 0; j < 2; j++) LDSM4(bf[j], sBhi + j * (16 * ROWB) + ko);
            #pragma unroll
            for (int i = 0; i < 4; i++)
                #pragma unroll
                for (int j = 0; j < 2; j++) {
                    MMA168(acc[i][j * 2 + 0], af[i], bf[j][0], bf[j][1]);
                    MMA168(acc[i][j * 2 + 1], af[i], bf[j][2], bf[j][3]);
                }
            // hi*lo
            uint32_t bl[2][4];
            #pragma unroll
            for (int j = 0; j < 2; j++) LDSM4(bl[j], sBlo + j * (16 * ROWB) + ko);
            #pragma unroll
            for (int i = 0; i < 4; i++)
                #pragma unroll
                for (int j = 0; j < 2; j++) {
                    MMA168(acc[i][j * 2 + 0], af[i], bl[j][0], bl[j][1]);
                    MMA168(acc[i][j * 2 + 1], af[i], bl[j][2], bl[j][3]);
                }
            // lo*hi
            #pragma unroll
            for (int i = 0; i < 4; i++) LDSM4(af[i], sAlo + i * (16 * ROWB) + ko);
            #pragma unroll
            for (int i = 0; i < 4; i++)
                #pragma unroll
                for (int j = 0; j < 2; j++) {
                    MMA168(acc[i][j * 2 + 0], af[i], bf[j][0], bf[j][1]);
                    MMA168(acc[i][j * 2 + 1], af[i], bf[j][2], bf[j][3]);
                }
        }
    }

    // ---- epilogue ----
    #pragma unroll
    for (int i = 0; i < 4; i++) {
        int row0 = bm + m0 + i * 16 + (lane >> 2);
        #pragma unroll
        for (int jj = 0; jj < 4; jj++) {
            int col = bn + n0 + jj * 8 + (lane & 3) * 2;
            float2 bv = *(const float2*)(bias + col);
            float2 r0, r1;
            r0.x = acc[i][jj][0] + bv.x;  r0.y = acc[i][jj][1] + bv.y;
            r1.x = acc[i][jj][2] + bv.x;  r1.y = acc[i][jj][3] + bv.y;
            *(float2*)(C + (size_t)row0 * DD + col) = r0;
            *(float2*)(C + (size_t)(row0 + 8) * DD + col) = r1;
        }
    }
}

// ---------------------------------------------------------------------------
// partial Kh^T @ Vh over 256-row s-chunks: grid (64, 8)
// ---------------------------------------------------------------------------
__global__ __launch_bounds__(256) void kv_outer() {
    int bh = blockIdx.x;
    int b = bh >> 4, h = bh & 15;
    int s_base = blockIdx.y * 256;
    const float* Kb = g_kh + (size_t)b * SS * DD + h * DKK;
    const float* Vb = g_vh + (size_t)b * SS * DD + h * DKK;

    __shared__ float ks[32][64];
    __shared__ float vs[32][64];

    int tid = threadIdx.x;
    int lrow = tid >> 3;
    int lcol = (tid & 7) << 3;
    int tj = (tid >> 4) << 2;
    int tk = (tid & 15) << 2;

    float acc[4][4];
    #pragma unroll
    for (int i = 0; i < 4; i++)
        #pragma unroll
        for (int j = 0; j < 4; j++) acc[i][j] = 0.0f;

    for (int s0 = s_base; s0 < s_base + 256; s0 += 32) {
        __syncthreads();
        const float* kp = Kb + (size_t)(s0 + lrow) * DD + lcol;
        const float* vp = Vb + (size_t)(s0 + lrow) * DD + lcol;
        *(float4*)&ks[lrow][lcol]     = *(const float4*)kp;
        *(float4*)&ks[lrow][lcol + 4] = *(const float4*)(kp + 4);
        *(float4*)&vs[lrow][lcol]     = *(const float4*)vp;
        *(float4*)&vs[lrow][lcol + 4] = *(const float4*)(vp + 4);
        __syncthreads();
        #pragma unroll
        for (int s = 0; s < 32; s++) {
            float4 kj4 = *(const float4*)&ks[s][tj];
            float4 vk4 = *(const float4*)&vs[s][tk];
            float kj[4] = {kj4.x, kj4.y, kj4.z, kj4.w};
            float vk[4] = {vk4.x, vk4.y, vk4.z, vk4.w};
            #pragma unroll
            for (int i = 0; i < 4; i++)
                #pragma unroll
                for (int j = 0; j < 4; j++)
                    acc[i][j] = fmaf(kj[i], vk[j], acc[i][j]);
        }
    }
    float* Mout = g_Mpart[bh * 8 + blockIdx.y];
    #pragma unroll
    for (int i = 0; i < 4; i++)
        #pragma unroll
        for (int j = 0; j < 4; j++)
            Mout[(tj + i) * DKK + tk + j] = acc[i][j];
}

__global__ __launch_bounds__(256) void reduce_M() {
    int bh = blockIdx.x;
    for (int e = threadIdx.x; e < DKK * DKK; e += 256) {
        float s = 0.0f;
        #pragma unroll
        for (int c = 0; c < 8; c++) s += g_Mpart[bh * 8 + c][e];
        g_M[bh][e] = s;
    }
}

// ---------------------------------------------------------------------------
// heads = softmax_k( (Qh @ M) / 8 ), written directly as tf32 hi/lo splits
// ---------------------------------------------------------------------------
__global__ __launch_bounds__(256) void qm_softmax() {
    int bh = blockIdx.x;
    int b = bh >> 4, h = bh & 15;

    __shared__ float Ms[DKK * DKK];
    __shared__ float qs[8][DKK];

    int tid = threadIdx.x;
    const float4* Msrc = (const float4*)g_M[bh];
    for (int i = tid; i < (DKK * DKK) / 4; i += 256)
        ((float4*)Ms)[i] = Msrc[i];
    __syncthreads();

    int warp = tid >> 5, lane = tid & 31;
    int sbase = blockIdx.y * 256;

    for (int it = 0; it < 32; it++) {
        int s = sbase + (it << 3) + warp;
        const float* qrow = g_qh + ((size_t)(b * SS + s)) * DD + h * DKK;
        qs[warp][lane]      = qrow[lane];
        qs[warp][lane + 32] = qrow[lane + 32];
        __syncwarp();

        float o0 = 0.0f, o1 = 0.0f;
        #pragma unroll
        for (int j = 0; j < 64; j++) {
            float qv = qs[warp][j];
            o0 = fmaf(qv, Ms[(j << 6) + lane],      o0);
            o1 = fmaf(qv, Ms[(j << 6) + lane + 32], o1);
        }
        o0 *= 0.125f;
        o1 *= 0.125f;

        float mx = fmaxf(o0, o1);
        #pragma unroll
        for (int off = 16; off; off >>= 1)
            mx = fmaxf(mx, __shfl_xor_sync(0xffffffffu, mx, off));
        float e0 = __expf(o0 - mx), e1 = __expf(o1 - mx);
        float sm = e0 + e1;
        #pragma unroll
        for (int off = 16; off; off >>= 1)
            sm += __shfl_xor_sync(0xffffffffu, sm, off);
        float inv = 1.0f / sm;

        size_t off0 = ((size_t)(b * SS + s)) * DD + h * DKK + lane;
        float v0 = e0 * inv, v1 = e1 * inv;
        float h0 = tf32r(v0), h1 = tf32r(v1);
        g_Ahi[off0]      = h0;  g_Alo[off0]      = tf32r(v0 - h0);
        g_Ahi[off0 + 32] = h1;  g_Alo[off0 + 32] = tf32r(v1 - h1);
        __syncwarp();
    }
}

// ---------------------------------------------------------------------------
extern "C" void kernel_launch(void* const* d_in, const int* in_sizes, int n_in,
                              void* d_out, int out_size) {
    const float* q    = (const float*)d_in[0];
    const float* k    = (const float*)d_in[1];
    const float* v    = (const float*)d_in[2];
    const float* wq_w = (const float*)d_in[3];
    const float* wq_b = (const float*)d_in[4];
    const float* wk_w = (const float*)d_in[5];
    const float* wk_b = (const float*)d_in[6];
    const float* wv_w = (const float*)d_in[7];
    const float* wv_b = (const float*)d_in[8];
    const float* wo_w = (const float*)d_in[9];
    const float* wo_b = (const float*)d_in[10];
    float* out = (float*)d_out;

    const int SMEM_BYTES = NSTG * STAGEB;   // 221184
    static int configured = 0;
    cudaFuncSetAttribute(mma_gemm, cudaFuncAttributeMaxDynamicSharedMemorySize, SMEM_BYTES);
    (void)configured;

    prep_split<<<(DD * DD) / 256, 256>>>(wq_w, wk_w, wv_w, wo_w);

    dim3 gg(DD / NT, MR / MT);   // (8, 64)
    split_src<<<(MR * DD) / 256, 256>>>(q);
    mma_gemm<<<gg, 256, SMEM_BYTES>>>(wq_b, nullptr, 0);
    split_src<<<(MR * DD) / 256, 256>>>(k);
    mma_gemm<<<gg, 256, SMEM_BYTES>>>(wk_b, nullptr, 1);
    split_src<<<(MR * DD) / 256, 256>>>(v);
    mma_gemm<<<gg, 256, SMEM_BYTES>>>(wv_b, nullptr, 2);

    kv_outer<<<dim3(BB * HH, 8), 256>>>();
    reduce_M<<<BB * HH, 256>>>();
    qm_softmax<<<dim3(BB * HH, SS / 256), 256>>>();   // writes g_Ahi/g_Alo

    mma_gemm<<<gg, 256, SMEM_BYTES>>>(wo_b, out, 3);
}

// round 5
// speedup vs baseline: 1.7484x; 1.2898x over previous
#include <cuda_runtime.h>
#include <cstdint>

#define BB 4
#define SS 2048
#define DD 1024
#define HH 16
#define DKK 64
#define MR (BB*SS)   // 8192

#define MT 128
#define NT 128
#define KC 32
#define NCH 32
#define TILEF 4096          // floats per 16KB tile
#define TILEB 16384
#define CHB (4*TILEB)       // stage bytes: Ahi|Alo|Bhi|Blo
#define NSTG 3

// ---------------- device scratch ----------------
__device__ float g_wt[4][2][DD*DD];     // weight panels [widx][hi/lo][(nt*32+ch)*4096 + sw]
__device__ float g_pan[4][2][MR*DD];    // activation panels: 0=q 1=k 2=v 3=softmax-out
__device__ float g_qh[MR*DD];
__device__ float g_kh[MR*DD];
__device__ float g_vh[MR*DD];
__device__ float g_Mpart[BB*HH*8][DKK*DKK];
__device__ float g_M[BB*HH][DKK*DKK];

// ---------------- helpers ----------------
__device__ __forceinline__ float tf32r(float x) {
    uint32_t u;
    asm("cvt.rna.tf32.f32 %0, %1;" : "=r"(u) : "f"(x));
    return __uint_as_float(u);
}
__device__ __forceinline__ uint32_t smem_u32(const void* p) {
    uint32_t a;
    asm("{ .reg .u64 t; cvta.to.shared.u64 t, %1; cvt.u32.u64 %0, t; }" : "=r"(a) : "l"(p));
    return a;
}
#define MBAR_INIT(a, c) asm volatile("mbarrier.init.shared.b64 [%0], %1;" :: "r"(a), "r"(c) : "memory")
#define MBAR_WAIT(a, ph) do { \
    asm volatile("{\n\t.reg .pred P;\n\tWL%=:\n\t" \
        "mbarrier.try_wait.parity.shared.b64 P, [%0], %1;\n\t" \
        "@!P bra WL%=;\n\t}" :: "r"(a), "r"(ph) : "memory"); } while (0)
#define EXPECT_TX(a, n) asm volatile( \
    "mbarrier.arrive.expect_tx.shared.b64 _, [%0], %1;" :: "r"(a), "r"(n) : "memory")
#define BULK(dst, src, n, bar) asm volatile( \
    "cp.async.bulk.shared::cluster.global.mbarrier::complete_tx::bytes [%0], [%1], %2, [%3];" \
    :: "r"(dst), "l"(src), "r"(n), "r"(bar) : "memory")
#define LDSM4(r, a) asm volatile( \
    "ldmatrix.sync.aligned.m8n8.x4.shared.b16 {%0,%1,%2,%3}, [%4];" \
    : "=r"((r)[0]), "=r"((r)[1]), "=r"((r)[2]), "=r"((r)[3]) : "r"(a))
#define MMA168(d, a, b0, b1) asm volatile( \
    "mma.sync.aligned.m16n8k8.row.col.f32.tf32.tf32.f32 " \
    "{%0,%1,%2,%3}, {%4,%5,%6,%7}, {%8,%9}, {%0,%1,%2,%3};" \
    : "+f"((d)[0]), "+f"((d)[1]), "+f"((d)[2]), "+f"((d)[3]) \
    : "r"((a)[0]), "r"((a)[1]), "r"((a)[2]), "r"((a)[3]), "r"(b0), "r"(b1))

// ---------------------------------------------------------------------------
// weights: split+transpose into pre-swizzled tf32 hi/lo panels
// ---------------------------------------------------------------------------
__global__ void prep_split(const float* __restrict__ wq, const float* __restrict__ wk,
                           const float* __restrict__ wv, const float* __restrict__ wo) {
    int idx = blockIdx.x * blockDim.x + threadIdx.x;   // n*1024 + k
    int n = idx >> 10, k = idx & 1023;
    int h = n >> 6, dk = n & 63;
    int src = h * (DD * DKK) + k * DKK + dk;           // w[h][k][dk]
    float v0 = wq[src], v1 = wk[src], v2 = wv[src], v3 = wo[n * DD + k];
    int nt = n >> 7, row = n & 127, ch = k >> 5, kk = k & 31;
    uint32_t off = row * 128 + kk * 4;
    uint32_t sw = off ^ ((off >> 3) & 0x70);
    size_t d = ((size_t)(nt * 32 + ch)) * TILEF + (sw >> 2);
    float h0 = tf32r(v0), h1 = tf32r(v1), h2 = tf32r(v2), h3 = tf32r(v3);
    g_wt[0][0][d] = h0; g_wt[0][1][d] = tf32r(v0 - h0);
    g_wt[1][0][d] = h1; g_wt[1][1][d] = tf32r(v1 - h1);
    g_wt[2][0][d] = h2; g_wt[2][1][d] = tf32r(v2 - h2);
    g_wt[3][0][d] = h3; g_wt[3][1][d] = tf32r(v3 - h3);
}

__device__ __forceinline__ void split_store(int w, float4 src, size_t d) {
    float4 hi, lo;
    hi.x = tf32r(src.x); lo.x = tf32r(src.x - hi.x);
    hi.y = tf32r(src.y); lo.y = tf32r(src.y - hi.y);
    hi.z = tf32r(src.z); lo.z = tf32r(src.z - hi.z);
    hi.w = tf32r(src.w); lo.w = tf32r(src.w - hi.w);
    *(float4*)&g_pan[w][0][d] = hi;
    *(float4*)&g_pan[w][1][d] = lo;
}

// split q,k,v into pre-swizzled hi/lo panels in one pass
__global__ void split3(const float* __restrict__ q, const float* __restrict__ k,
                       const float* __restrict__ v) {
    int idx4 = blockIdx.x * blockDim.x + threadIdx.x;  // float4 index
    int m = idx4 >> 8;
    int kc = (idx4 & 255) << 2;
    int mt = m >> 7, row = m & 127, ch = kc >> 5, kk = kc & 31;
    uint32_t off = row * 128 + kk * 4;
    uint32_t sw = off ^ ((off >> 3) & 0x70);
    size_t d = ((size_t)(mt * 32 + ch)) * TILEF + (sw >> 2);
    size_t s = (size_t)idx4 * 4;
    split_store(0, *(const float4*)(q + s), d);
    split_store(1, *(const float4*)(k + s), d);
    split_store(2, *(const float4*)(v + s), d);
}

// ---------------------------------------------------------------------------
// 3xTF32 mma.sync GEMM, bulk-copy pipeline: C[8192,1024] = A @ W^T + bias
// ---------------------------------------------------------------------------
__global__ __launch_bounds__(256) void mma_gemm(const float* __restrict__ bias,
                                                float* __restrict__ Cout, int widx) {
    extern __shared__ char smem[];
    float* C = (widx == 0) ? g_qh : (widx == 1) ? g_kh : (widx == 2) ? g_vh : Cout;
    const float* Ahi = g_pan[widx][0];
    const float* Alo = g_pan[widx][1];
    const float* Bhi = g_wt[widx][0];
    const float* Blo = g_wt[widx][1];

    const uint32_t s0 = smem_u32(smem);
    const uint32_t mb = s0 + NSTG * CHB;

    const int tid = threadIdx.x;
    const int wid = tid >> 5, lane = tid & 31;
    const int bm = blockIdx.y * MT, bn = blockIdx.x * NT;
    const int m0 = (wid >> 2) * 64;
    const int n0 = (wid & 3) * 32;

    if (tid == 0) { MBAR_INIT(mb, 1); MBAR_INIT(mb + 8, 1); MBAR_INIT(mb + 16, 1); }
    __syncthreads();

    auto issue = [&](int ch, int stg) {
        uint32_t sb = s0 + stg * CHB;
        uint32_t bar = mb + stg * 8;
        EXPECT_TX(bar, (uint32_t)CHB);
        const float* a0 = Ahi + ((size_t)(blockIdx.y * 32 + ch)) * TILEF;
        const float* a1 = Alo + ((size_t)(blockIdx.y * 32 + ch)) * TILEF;
        const float* b0 = Bhi + ((size_t)(blockIdx.x * 32 + ch)) * TILEF;
        const float* b1 = Blo + ((size_t)(blockIdx.x * 32 + ch)) * TILEF;
        BULK(sb,             a0, TILEB, bar);
        BULK(sb + TILEB,     a1, TILEB, bar);
        BULK(sb + 2 * TILEB, b0, TILEB, bar);
        BULK(sb + 3 * TILEB, b1, TILEB, bar);
    };
    if (tid == 0) { issue(0, 0); issue(1, 1); }

    // ldmatrix lane addressing (swizzled)
    const int arow = (lane & 7) + ((lane >> 3) & 1) * 8;
    const uint32_t akoff = (lane >> 4) * 16;
    const int nrow = (lane & 7) + (lane >> 4) * 8;
    const uint32_t bkoff = ((lane >> 3) & 1) * 16;
    const uint32_t xswA = ((uint32_t)(m0 + arow) & 7) << 4;
    const uint32_t xswB = ((uint32_t)(n0 + nrow) & 7) << 4;
    const uint32_t aBase = (uint32_t)(m0 + arow) * 128;
    const uint32_t bBase = (uint32_t)(n0 + nrow) * 128;

    float acc[4][4][4];
    #pragma unroll
    for (int i = 0; i < 4; i++)
        #pragma unroll
        for (int j = 0; j < 4; j++)
            #pragma unroll
            for (int r = 0; r < 4; r++) acc[i][j][r] = 0.0f;

    for (int c = 0; c < NCH; ++c) {
        int stg = c % 3;
        uint32_t sb = s0 + stg * CHB;
        MBAR_WAIT(mb + stg * 8, (c / 3) & 1);

        #pragma unroll
        for (int ks = 0; ks < 4; ks++) {
            const uint32_t kaA = ((uint32_t)(ks * 32) + akoff) ^ xswA;
            const uint32_t kaB = ((uint32_t)(ks * 32) + bkoff) ^ xswB;
            uint32_t af[4][4], bf[2][4], bl[2][4];
            // hi*hi
            #pragma unroll
            for (int i = 0; i < 4; i++) LDSM4(af[i], sb + aBase + i * 2048 + kaA);
            #pragma unroll
            for (int j = 0; j < 2; j++) LDSM4(bf[j], sb + 2 * TILEB + bBase + j * 2048 + kaB);
            #pragma unroll
            for (int i = 0; i < 4; i++)
                #pragma unroll
                for (int j = 0; j < 2; j++) {
                    MMA168(acc[i][j * 2 + 0], af[i], bf[j][0], bf[j][1]);
                    MMA168(acc[i][j * 2 + 1], af[i], bf[j][2], bf[j][3]);
                }
            // hi*lo
            #pragma unroll
            for (int j = 0; j < 2; j++) LDSM4(bl[j], sb + 3 * TILEB + bBase + j * 2048 + kaB);
            #pragma unroll
            for (int i = 0; i < 4; i++)
                #pragma unroll
                for (int j = 0; j < 2; j++) {
                    MMA168(acc[i][j * 2 + 0], af[i], bl[j][0], bl[j][1]);
                    MMA168(acc[i][j * 2 + 1], af[i], bl[j][2], bl[j][3]);
                }
            // lo*hi
            #pragma unroll
            for (int i = 0; i < 4; i++) LDSM4(af[i], sb + TILEB + aBase + i * 2048 + kaA);
            #pragma unroll
            for (int i = 0; i < 4; i++)
                #pragma unroll
                for (int j = 0; j < 2; j++) {
                    MMA168(acc[i][j * 2 + 0], af[i], bf[j][0], bf[j][1]);
                    MMA168(acc[i][j * 2 + 1], af[i], bf[j][2], bf[j][3]);
                }
        }
        __syncthreads();
        if (tid == 0 && c + 2 < NCH) issue(c + 2, (c + 2) % 3);
    }

    // ---- epilogue ----
    #pragma unroll
    for (int i = 0; i < 4; i++) {
        int row0 = bm + m0 + i * 16 + (lane >> 2);
        #pragma unroll
        for (int jj = 0; jj < 4; jj++) {
            int col = bn + n0 + jj * 8 + (lane & 3) * 2;
            float2 bv = *(const float2*)(bias + col);
            float2 r0, r1;
            r0.x = acc[i][jj][0] + bv.x;  r0.y = acc[i][jj][1] + bv.y;
            r1.x = acc[i][jj][2] + bv.x;  r1.y = acc[i][jj][3] + bv.y;
            *(float2*)(C + (size_t)row0 * DD + col) = r0;
            *(float2*)(C + (size_t)(row0 + 8) * DD + col) = r1;
        }
    }
}

// ---------------------------------------------------------------------------
// partial Kh^T @ Vh over 256-row s-chunks: grid (64, 8)
// ---------------------------------------------------------------------------
__global__ __launch_bounds__(256) void kv_outer() {
    int bh = blockIdx.x;
    int b = bh >> 4, h = bh & 15;
    int s_base = blockIdx.y * 256;
    const float* Kb = g_kh + (size_t)b * SS * DD + h * DKK;
    const float* Vb = g_vh + (size_t)b * SS * DD + h * DKK;

    __shared__ float ks[32][64];
    __shared__ float vs[32][64];

    int tid = threadIdx.x;
    int lrow = tid >> 3;
    int lcol = (tid & 7) << 3;
    int tj = (tid >> 4) << 2;
    int tk = (tid & 15) << 2;

    float acc[4][4];
    #pragma unroll
    for (int i = 0; i < 4; i++)
        #pragma unroll
        for (int j = 0; j < 4; j++) acc[i][j] = 0.0f;

    for (int s0 = s_base; s0 < s_base + 256; s0 += 32) {
        __syncthreads();
        const float* kp = Kb + (size_t)(s0 + lrow) * DD + lcol;
        const float* vp = Vb + (size_t)(s0 + lrow) * DD + lcol;
        *(float4*)&ks[lrow][lcol]     = *(const float4*)kp;
        *(float4*)&ks[lrow][lcol + 4] = *(const float4*)(kp + 4);
        *(float4*)&vs[lrow][lcol]     = *(const float4*)vp;
        *(float4*)&vs[lrow][lcol + 4] = *(const float4*)(vp + 4);
        __syncthreads();
        #pragma unroll
        for (int s = 0; s < 32; s++) {
            float4 kj4 = *(const float4*)&ks[s][tj];
            float4 vk4 = *(const float4*)&vs[s][tk];
            float kj[4] = {kj4.x, kj4.y, kj4.z, kj4.w};
            float vk[4] = {vk4.x, vk4.y, vk4.z, vk4.w};
            #pragma unroll
            for (int i = 0; i < 4; i++)
                #pragma unroll
                for (int j = 0; j < 4; j++)
                    acc[i][j] = fmaf(kj[i], vk[j], acc[i][j]);
        }
    }
    float* Mout = g_Mpart[bh * 8 + blockIdx.y];
    #pragma unroll
    for (int i = 0; i < 4; i++)
        #pragma unroll
        for (int j = 0; j < 4; j++)
            Mout[(tj + i) * DKK + tk + j] = acc[i][j];
}

__global__ __launch_bounds__(256) void reduce_M() {
    int bh = blockIdx.x;
    for (int e = threadIdx.x; e < DKK * DKK; e += 256) {
        float s = 0.0f;
        #pragma unroll
        for (int c = 0; c < 8; c++) s += g_Mpart[bh * 8 + c][e];
        g_M[bh][e] = s;
    }
}

// ---------------------------------------------------------------------------
// heads = softmax_k( (Qh @ M) / 8 ), written directly as swizzled hi/lo panels
// ---------------------------------------------------------------------------
__global__ __launch_bounds__(256) void qm_softmax() {
    int bh = blockIdx.x;
    int b = bh >> 4, h = bh & 15;

    __shared__ float Ms[DKK * DKK];
    __shared__ float qs[8][DKK];

    int tid = threadIdx.x;
    const float4* Msrc = (const float4*)g_M[bh];
    for (int i = tid; i < (DKK * DKK) / 4; i += 256)
        ((float4*)Ms)[i] = Msrc[i];
    __syncthreads();

    int warp = tid >> 5, lane = tid & 31;
    int sbase = blockIdx.y * 256;

    for (int it = 0; it < 32; it++) {
        int s = sbase + (it << 3) + warp;
        const float* qrow = g_qh + ((size_t)(b * SS + s)) * DD + h * DKK;
        qs[warp][lane]      = qrow[lane];
        qs[warp][lane + 32] = qrow[lane + 32];
        __syncwarp();

        float o0 = 0.0f, o1 = 0.0f;
        #pragma unroll
        for (int j = 0; j < 64; j++) {
            float qv = qs[warp][j];
            o0 = fmaf(qv, Ms[(j << 6) + lane],      o0);
            o1 = fmaf(qv, Ms[(j << 6) + lane + 32], o1);
        }
        o0 *= 0.125f;
        o1 *= 0.125f;

        float mx = fmaxf(o0, o1);
        #pragma unroll
        for (int off = 16; off; off >>= 1)
            mx = fmaxf(mx, __shfl_xor_sync(0xffffffffu, mx, off));
        float e0 = __expf(o0 - mx), e1 = __expf(o1 - mx);
        float sm = e0 + e1;
        #pragma unroll
        for (int off = 16; off; off >>= 1)
            sm += __shfl_xor_sync(0xffffffffu, sm, off);
        float inv = 1.0f / sm;

        // write to panel layout (pre-swizzled hi/lo)
        int mrow = b * SS + s;
        int mt = mrow >> 7, prow = mrow & 127;
        uint32_t off0 = (uint32_t)prow * 128 + lane * 4;
        uint32_t sw0 = off0 ^ ((off0 >> 3) & 0x70);
        size_t d0 = ((size_t)(mt * 32 + h * 2))     * TILEF + (sw0 >> 2);
        size_t d1 = ((size_t)(mt * 32 + h * 2 + 1)) * TILEF + (sw0 >> 2);
        float v0 = e0 * inv, v1 = e1 * inv;
        float h0 = tf32r(v0), h1 = tf32r(v1);
        g_pan[3][0][d0] = h0;  g_pan[3][1][d0] = tf32r(v0 - h0);
        g_pan[3][0][d1] = h1;  g_pan[3][1][d1] = tf32r(v1 - h1);
        __syncwarp();
    }
}

// ---------------------------------------------------------------------------
extern "C" void kernel_launch(void* const* d_in, const int* in_sizes, int n_in,
                              void* d_out, int out_size) {
    const float* q    = (const float*)d_in[0];
    const float* k    = (const float*)d_in[1];
    const float* v    = (const float*)d_in[2];
    const float* wq_w = (const float*)d_in[3];
    const float* wq_b = (const float*)d_in[4];
    const float* wk_w = (const float*)d_in[5];
    const float* wk_b = (const float*)d_in[6];
    const float* wv_w = (const float*)d_in[7];
    const float* wv_b = (const float*)d_in[8];
    const float* wo_w = (const float*)d_in[9];
    const float* wo_b = (const float*)d_in[10];
    float* out = (float*)d_out;

    const int SMEM_BYTES = NSTG * CHB + 64;   // 196672
    cudaFuncSetAttribute(mma_gemm, cudaFuncAttributeMaxDynamicSharedMemorySize, SMEM_BYTES);

    prep_split<<<(DD * DD) / 256, 256>>>(wq_w, wk_w, wv_w, wo_w);
    split3<<<(MR * DD / 4) / 256, 256>>>(q, k, v);

    dim3 gg(DD / NT, MR / MT);   // (8, 64)
    mma_gemm<<<gg, 256, SMEM_BYTES>>>(wq_b, nullptr, 0);
    mma_gemm<<<gg, 256, SMEM_BYTES>>>(wk_b, nullptr, 1);
    mma_gemm<<<gg, 256, SMEM_BYTES>>>(wv_b, nullptr, 2);

    kv_outer<<<dim3(BB * HH, 8), 256>>>();
    reduce_M<<<BB * HH, 256>>>();
    qm_softmax<<<dim3(BB * HH, SS / 256), 256>>>();   // writes g_pan[3]

    mma_gemm<<<gg, 256, SMEM_BYTES>>>(wo_b, out, 3);
}

// round 6
// speedup vs baseline: 3.3082x; 1.8922x over previous
#include <cuda_runtime.h>
#include <cuda_fp16.h>
#include <cstdint>

#define BB 4
#define SS 2048
#define DD 1024
#define HH 16
#define DKK 64
#define MR (BB*SS)   // 8192

#define MT 128
#define NT 128
#define NCH 32
#define TILEH 4096           // halves per 128x32 tile
#define TILEB 8192           // bytes per tile
#define CHB (4*TILEB)        // stage: Ahi|Alo|Bhi|Blo = 32KB
#define NSTG 3

// ---------------- device scratch ----------------
__device__ __half g_wt[4][2][DD*DD];    // weight panels (x32 scaled, split hi/lo)
__device__ __half g_pan[4][2][MR*DD];   // activation panels: 0=q 1=k 2=v 3=softmax-out
__device__ float g_qh[MR*DD];
__device__ float g_kh[MR*DD];
__device__ float g_vh[MR*DD];
__device__ float g_Mpart[BB*HH*8][DKK*DKK];
__device__ float g_M[BB*HH][DKK*DKK];

// ---------------- helpers ----------------
__device__ __forceinline__ uint32_t smem_u32(const void* p) {
    uint32_t a;
    asm("{ .reg .u64 t; cvta.to.shared.u64 t, %1; cvt.u32.u64 %0, t; }" : "=r"(a) : "l"(p));
    return a;
}
#define MBAR_INIT(a, c) asm volatile("mbarrier.init.shared.b64 [%0], %1;" :: "r"(a), "r"(c) : "memory")
#define MBAR_WAIT(a, ph) do { \
    asm volatile("{\n\t.reg .pred P;\n\tWL%=:\n\t" \
        "mbarrier.try_wait.parity.shared.b64 P, [%0], %1;\n\t" \
        "@!P bra WL%=;\n\t}" :: "r"(a), "r"(ph) : "memory"); } while (0)
#define EXPECT_TX(a, n) asm volatile( \
    "mbarrier.arrive.expect_tx.shared.b64 _, [%0], %1;" :: "r"(a), "r"(n) : "memory")
#define BULK(dst, src, n, bar) asm volatile( \
    "cp.async.bulk.shared::cluster.global.mbarrier::complete_tx::bytes [%0], [%1], %2, [%3];" \
    :: "r"(dst), "l"(src), "r"(n), "r"(bar) : "memory")
#define LDSM4(r, a) asm volatile( \
    "ldmatrix.sync.aligned.m8n8.x4.shared.b16 {%0,%1,%2,%3}, [%4];" \
    : "=r"((r)[0]), "=r"((r)[1]), "=r"((r)[2]), "=r"((r)[3]) : "r"(a))
#define MMAF16(d, a, b0, b1) asm volatile( \
    "mma.sync.aligned.m16n8k16.row.col.f32.f16.f16.f32 " \
    "{%0,%1,%2,%3}, {%4,%5,%6,%7}, {%8,%9}, {%0,%1,%2,%3};" \
    : "+f"((d)[0]), "+f"((d)[1]), "+f"((d)[2]), "+f"((d)[3]) \
    : "r"((a)[0]), "r"((a)[1]), "r"((a)[2]), "r"((a)[3]), "r"(b0), "r"(b1))

// SW64-style swizzle for 64B rows: XOR 16B-chunk index with row bits [1:2]
__device__ __forceinline__ uint32_t sw64(uint32_t off) {
    return off ^ ((off >> 3) & 0x30);
}

// ---------------------------------------------------------------------------
// weights: scale x32, split+transpose into pre-swizzled fp16 hi/lo panels
// ---------------------------------------------------------------------------
__global__ void prep_split(const float* __restrict__ wq, const float* __restrict__ wk,
                           const float* __restrict__ wv, const float* __restrict__ wo) {
    int idx = blockIdx.x * blockDim.x + threadIdx.x;   // n*1024 + k
    int n = idx >> 10, k = idx & 1023;
    int h = n >> 6, dk = n & 63;
    int src = h * (DD * DKK) + k * DKK + dk;           // w[h][k][dk]
    uint32_t off = (n & 127) * 64 + (k & 31) * 2;
    size_t d = ((size_t)((n >> 7) * 32 + (k >> 5))) * TILEH + (sw64(off) >> 1);
    float vals[4] = { wq[src] * 32.0f, wk[src] * 32.0f, wv[src] * 32.0f,
                      wo[n * DD + k] * 32.0f };
    #pragma unroll
    for (int w = 0; w < 4; w++) {
        __half hi = __float2half_rn(vals[w]);
        __half lo = __float2half_rn(vals[w] - __half2float(hi));
        g_wt[w][0][d] = hi;
        g_wt[w][1][d] = lo;
    }
}

// split q,k,v into pre-swizzled fp16 hi/lo panels; one 16B chunk per thread
__global__ void split3(const float* __restrict__ q, const float* __restrict__ k,
                       const float* __restrict__ v) {
    int idx = blockIdx.x * blockDim.x + threadIdx.x;   // chunk index (8 halves)
    int m = idx >> 7;
    int k0 = (idx & 127) << 3;
    uint32_t off = (m & 127) * 64 + (k0 & 31) * 2;
    size_t d = ((size_t)((m >> 7) * 32 + (k0 >> 5))) * TILEH + (sw64(off) >> 1);
    size_t s = (size_t)m * DD + k0;
    const float* srcs[3] = { q + s, k + s, v + s };
    #pragma unroll
    for (int w = 0; w < 3; w++) {
        float f[8];
        *(float4*)&f[0] = *(const float4*)(srcs[w]);
        *(float4*)&f[4] = *(const float4*)(srcs[w] + 4);
        __half hi[8], lo[8];
        #pragma unroll
        for (int i = 0; i < 8; i++) {
            hi[i] = __float2half_rn(f[i]);
            lo[i] = __float2half_rn(f[i] - __half2float(hi[i]));
        }
        *(uint4*)&g_pan[w][0][d] = *(uint4*)hi;
        *(uint4*)&g_pan[w][1][d] = *(uint4*)lo;
    }
}

// ---------------------------------------------------------------------------
// 3x-split fp16 mma.sync GEMM, bulk-copy pipeline.
// mode 0: fused QKV (grid.x=24 -> widx = x>>3), mode 1: wo (widx=3).
// ---------------------------------------------------------------------------
__global__ __launch_bounds__(256, 2) void mma_gemm(
        const float* __restrict__ b0p, const float* __restrict__ b1p,
        const float* __restrict__ b2p, const float* __restrict__ bwp,
        float* __restrict__ Oout, int mode) {
    extern __shared__ char smem[];
    int widx, nIdx;
    const float* bias;
    float* C;
    if (mode == 0) {
        widx = blockIdx.x >> 3;
        nIdx = blockIdx.x & 7;
        bias = (widx == 0) ? b0p : (widx == 1) ? b1p : b2p;
        C = (widx == 0) ? g_qh : (widx == 1) ? g_kh : g_vh;
    } else {
        widx = 3;
        nIdx = blockIdx.x;
        bias = bwp;
        C = Oout;
    }
    const __half* Ahi = g_pan[widx][0];
    const __half* Alo = g_pan[widx][1];
    const __half* Bhi = g_wt[widx][0];
    const __half* Blo = g_wt[widx][1];

    const uint32_t s0 = smem_u32(smem);
    const uint32_t mb = s0 + NSTG * CHB;

    const int tid = threadIdx.x;
    const int wid = tid >> 5, lane = tid & 31;
    const int bm = blockIdx.y * MT, bn = nIdx * NT;
    const int m0 = (wid >> 2) * 64;
    const int n0 = (wid & 3) * 32;

    if (tid == 0) { MBAR_INIT(mb, 1); MBAR_INIT(mb + 8, 1); MBAR_INIT(mb + 16, 1); }
    __syncthreads();

    auto issue = [&](int ch, int stg) {
        uint32_t sb = s0 + stg * CHB;
        uint32_t bar = mb + stg * 8;
        EXPECT_TX(bar, (uint32_t)CHB);
        const __half* a0 = Ahi + ((size_t)(blockIdx.y * 32 + ch)) * TILEH;
        const __half* a1 = Alo + ((size_t)(blockIdx.y * 32 + ch)) * TILEH;
        const __half* w0 = Bhi + ((size_t)(nIdx * 32 + ch)) * TILEH;
        const __half* w1 = Blo + ((size_t)(nIdx * 32 + ch)) * TILEH;
        BULK(sb,             a0, TILEB, bar);
        BULK(sb + TILEB,     a1, TILEB, bar);
        BULK(sb + 2 * TILEB, w0, TILEB, bar);
        BULK(sb + 3 * TILEB, w1, TILEB, bar);
    };
    if (tid == 0) { issue(0, 0); issue(1, 1); }

    // ldmatrix lane addressing (64B rows, sw64 swizzle)
    const int rowA = m0 + (lane & 7) + ((lane >> 3) & 1) * 8;
    const uint32_t cA = ((lane >> 4) & 1) * 16;
    const uint32_t xswA = (uint32_t)(rowA & 6) << 3;
    const uint32_t aRow = (uint32_t)rowA * 64;
    const int rowB = n0 + ((lane >> 4) << 3) + (lane & 7);
    const uint32_t cB = ((lane >> 3) & 1) * 16;
    const uint32_t xswB = (uint32_t)(rowB & 6) << 3;
    const uint32_t bRow = (uint32_t)rowB * 64;

    float acc[4][4][4];
    #pragma unroll
    for (int i = 0; i < 4; i++)
        #pragma unroll
        for (int j = 0; j < 4; j++)
            #pragma unroll
            for (int r = 0; r < 4; r++) acc[i][j][r] = 0.0f;

    for (int c = 0; c < NCH; ++c) {
        int stg = c % 3;
        uint32_t sb = s0 + stg * CHB;
        MBAR_WAIT(mb + stg * 8, (c / 3) & 1);

        #pragma unroll
        for (int ks = 0; ks < 2; ks++) {
            const uint32_t aoff = aRow + (((uint32_t)(ks * 32) + cA) ^ xswA);
            const uint32_t boff = bRow + (((uint32_t)(ks * 32) + cB) ^ xswB);
            uint32_t ah[4][4], al[4][4], bh[2][4], bl[2][4];
            // hi*hi
            #pragma unroll
            for (int i = 0; i < 4; i++) LDSM4(ah[i], sb + aoff + i * 1024);
            #pragma unroll
            for (int g = 0; g < 2; g++) LDSM4(bh[g], sb + 2 * TILEB + boff + g * 1024);
            #pragma unroll
            for (int i = 0; i < 4; i++) {
                MMAF16(acc[i][0], ah[i], bh[0][0], bh[0][1]);
                MMAF16(acc[i][1], ah[i], bh[0][2], bh[0][3]);
                MMAF16(acc[i][2], ah[i], bh[1][0], bh[1][1]);
                MMAF16(acc[i][3], ah[i], bh[1][2], bh[1][3]);
            }
            // hi*lo
            #pragma unroll
            for (int g = 0; g < 2; g++) LDSM4(bl[g], sb + 3 * TILEB + boff + g * 1024);
            #pragma unroll
            for (int i = 0; i < 4; i++) {
                MMAF16(acc[i][0], ah[i], bl[0][0], bl[0][1]);
                MMAF16(acc[i][1], ah[i], bl[0][2], bl[0][3]);
                MMAF16(acc[i][2], ah[i], bl[1][0], bl[1][1]);
                MMAF16(acc[i][3], ah[i], bl[1][2], bl[1][3]);
            }
            // lo*hi
            #pragma unroll
            for (int i = 0; i < 4; i++) LDSM4(al[i], sb + TILEB + aoff + i * 1024);
            #pragma unroll
            for (int i = 0; i < 4; i++) {
                MMAF16(acc[i][0], al[i], bh[0][0], bh[0][1]);
                MMAF16(acc[i][1], al[i], bh[0][2], bh[0][3]);
                MMAF16(acc[i][2], al[i], bh[1][0], bh[1][1]);
                MMAF16(acc[i][3], al[i], bh[1][2], bh[1][3]);
            }
        }
        __syncthreads();
        if (tid == 0 && c + 2 < NCH) issue(c + 2, (c + 2) % 3);
    }

    // ---- epilogue: undo x32 weight scale, add bias ----
    #pragma unroll
    for (int i = 0; i < 4; i++) {
        int row0 = bm + m0 + i * 16 + (lane >> 2);
        #pragma unroll
        for (int jj = 0; jj < 4; jj++) {
            int col = bn + n0 + jj * 8 + (lane & 3) * 2;
            float2 bv = *(const float2*)(bias + col);
            float2 r0, r1;
            r0.x = acc[i][jj][0] * 0.03125f + bv.x;  r0.y = acc[i][jj][1] * 0.03125f + bv.y;
            r1.x = acc[i][jj][2] * 0.03125f + bv.x;  r1.y = acc[i][jj][3] * 0.03125f + bv.y;
            *(float2*)(C + (size_t)row0 * DD + col) = r0;
            *(float2*)(C + (size_t)(row0 + 8) * DD + col) = r1;
        }
    }
}

// ---------------------------------------------------------------------------
// partial Kh^T @ Vh over 256-row s-chunks: grid (64, 8)
// ---------------------------------------------------------------------------
__global__ __launch_bounds__(256) void kv_outer() {
    int bh = blockIdx.x;
    int b = bh >> 4, h = bh & 15;
    int s_base = blockIdx.y * 256;
    const float* Kb = g_kh + (size_t)b * SS * DD + h * DKK;
    const float* Vb = g_vh + (size_t)b * SS * DD + h * DKK;

    __shared__ float ks[32][64];
    __shared__ float vs[32][64];

    int tid = threadIdx.x;
    int lrow = tid >> 3;
    int lcol = (tid & 7) << 3;
    int tj = (tid >> 4) << 2;
    int tk = (tid & 15) << 2;

    float acc[4][4];
    #pragma unroll
    for (int i = 0; i < 4; i++)
        #pragma unroll
        for (int j = 0; j < 4; j++) acc[i][j] = 0.0f;

    for (int s0 = s_base; s0 < s_base + 256; s0 += 32) {
        __syncthreads();
        const float* kp = Kb + (size_t)(s0 + lrow) * DD + lcol;
        const float* vp = Vb + (size_t)(s0 + lrow) * DD + lcol;
        *(float4*)&ks[lrow][lcol]     = *(const float4*)kp;
        *(float4*)&ks[lrow][lcol + 4] = *(const float4*)(kp + 4);
        *(float4*)&vs[lrow][lcol]     = *(const float4*)vp;
        *(float4*)&vs[lrow][lcol + 4] = *(const float4*)(vp + 4);
        __syncthreads();
        #pragma unroll
        for (int s = 0; s < 32; s++) {
            float4 kj4 = *(const float4*)&ks[s][tj];
            float4 vk4 = *(const float4*)&vs[s][tk];
            float kj[4] = {kj4.x, kj4.y, kj4.z, kj4.w};
            float vk[4] = {vk4.x, vk4.y, vk4.z, vk4.w};
            #pragma unroll
            for (int i = 0; i < 4; i++)
                #pragma unroll
                for (int j = 0; j < 4; j++)
                    acc[i][j] = fmaf(kj[i], vk[j], acc[i][j]);
        }
    }
    float* Mout = g_Mpart[bh * 8 + blockIdx.y];
    #pragma unroll
    for (int i = 0; i < 4; i++)
        #pragma unroll
        for (int j = 0; j < 4; j++)
            Mout[(tj + i) * DKK + tk + j] = acc[i][j];
}

__global__ __launch_bounds__(256) void reduce_M() {
    int bh = blockIdx.x;
    for (int e = threadIdx.x; e < DKK * DKK; e += 256) {
        float s = 0.0f;
        #pragma unroll
        for (int c = 0; c < 8; c++) s += g_Mpart[bh * 8 + c][e];
        g_M[bh][e] = s;
    }
}

// ---------------------------------------------------------------------------
// heads = softmax_k( (Qh @ M) / 8 ), written as swizzled fp16 hi/lo panels
// ---------------------------------------------------------------------------
__global__ __launch_bounds__(256) void qm_softmax() {
    int bh = blockIdx.x;
    int b = bh >> 4, h = bh & 15;

    __shared__ float Ms[DKK * DKK];
    __shared__ float qs[8][DKK];

    int tid = threadIdx.x;
    const float4* Msrc = (const float4*)g_M[bh];
    for (int i = tid; i < (DKK * DKK) / 4; i += 256)
        ((float4*)Ms)[i] = Msrc[i];
    __syncthreads();

    int warp = tid >> 5, lane = tid & 31;
    int sbase = blockIdx.y * 128;

    for (int it = 0; it < 16; it++) {
        int s = sbase + (it << 3) + warp;
        const float* qrow = g_qh + ((size_t)(b * SS + s)) * DD + h * DKK;
        qs[warp][lane]      = qrow[lane];
        qs[warp][lane + 32] = qrow[lane + 32];
        __syncwarp();

        float o0 = 0.0f, o1 = 0.0f;
        #pragma unroll
        for (int j = 0; j < 64; j++) {
            float qv = qs[warp][j];
            o0 = fmaf(qv, Ms[(j << 6) + lane],      o0);
            o1 = fmaf(qv, Ms[(j << 6) + lane + 32], o1);
        }
        o0 *= 0.125f;
        o1 *= 0.125f;

        float mx = fmaxf(o0, o1);
        #pragma unroll
        for (int off = 16; off; off >>= 1)
            mx = fmaxf(mx, __shfl_xor_sync(0xffffffffu, mx, off));
        float e0 = __expf(o0 - mx), e1 = __expf(o1 - mx);
        float sm = e0 + e1;
        #pragma unroll
        for (int off = 16; off; off >>= 1)
            sm += __shfl_xor_sync(0xffffffffu, sm, off);
        float inv = 1.0f / sm;

        // write to fp16 panel layout (pre-swizzled hi/lo)
        int mrow = b * SS + s;
        int mt = mrow >> 7, prow = mrow & 127;
        uint32_t off0 = (uint32_t)prow * 64 + lane * 2;
        uint32_t sw0 = sw64(off0) >> 1;
        size_t d0 = ((size_t)(mt * 32 + h * 2))     * TILEH + sw0;
        size_t d1 = ((size_t)(mt * 32 + h * 2 + 1)) * TILEH + sw0;
        float v0 = e0 * inv, v1 = e1 * inv;
        __half h0 = __float2half_rn(v0);
        __half h1 = __float2half_rn(v1);
        g_pan[3][0][d0] = h0;  g_pan[3][1][d0] = __float2half_rn(v0 - __half2float(h0));
        g_pan[3][0][d1] = h1;  g_pan[3][1][d1] = __float2half_rn(v1 - __half2float(h1));
        __syncwarp();
    }
}

// ---------------------------------------------------------------------------
extern "C" void kernel_launch(void* const* d_in, const int* in_sizes, int n_in,
                              void* d_out, int out_size) {
    const float* q    = (const float*)d_in[0];
    const float* k    = (const float*)d_in[1];
    const float* v    = (const float*)d_in[2];
    const float* wq_w = (const float*)d_in[3];
    const float* wq_b = (const float*)d_in[4];
    const float* wk_w = (const float*)d_in[5];
    const float* wk_b = (const float*)d_in[6];
    const float* wv_w = (const float*)d_in[7];
    const float* wv_b = (const float*)d_in[8];
    const float* wo_w = (const float*)d_in[9];
    const float* wo_b = (const float*)d_in[10];
    float* out = (float*)d_out;

    const int SMEM_BYTES = NSTG * CHB + 64;   // 98368
    cudaFuncSetAttribute(mma_gemm, cudaFuncAttributeMaxDynamicSharedMemorySize, SMEM_BYTES);

    prep_split<<<(DD * DD) / 256, 256>>>(wq_w, wk_w, wv_w, wo_w);
    split3<<<(MR * DD / 8) / 256, 256>>>(q, k, v);

    // fused QKV projection GEMMs
    mma_gemm<<<dim3(24, 64), 256, SMEM_BYTES>>>(wq_b, wk_b, wv_b, nullptr, nullptr, 0);

    kv_outer<<<dim3(BB * HH, 8), 256>>>();
    reduce_M<<<BB * HH, 256>>>();
    qm_softmax<<<dim3(BB * HH, SS / 128), 256>>>();   // writes g_pan[3]

    // output projection
    mma_gemm<<<dim3(8, 64), 256, SMEM_BYTES>>>(nullptr, nullptr, nullptr, wo_b, out, 1);
}